// round 2
// baseline (speedup 1.0000x reference)
#include <cuda_runtime.h>
#include <math.h>

#define N_FFT   16000
#define BATCH   512
#define D_IN    2048
#define ODIM    3000
#define KDIM    16000

// Scratch (device globals — allocation-free per harness rules)
__device__ float2 g_CBUF[BATCH * N_FFT];   // 64 MB: packed sketch / spectrum
__device__ float  g_ZBUF[BATCH * N_FFT];   // 32 MB: conv result z
__device__ float2 g_TW[N_FFT];             // twiddle table exp(-2*pi*i*j/N)

static __device__ __forceinline__ float2 cmulf(float2 a, float2 b) {
    return make_float2(a.x * b.x - a.y * b.y, a.x * b.y + a.y * b.x);
}

// ---------------------------------------------------------------------------
// Twiddle init (double precision for table accuracy)
// ---------------------------------------------------------------------------
__global__ void tw_init_kernel() {
    int j = blockIdx.x * blockDim.x + threadIdx.x;
    if (j < N_FFT) {
        double ang = -2.0 * 3.14159265358979323846 * (double)j / (double)N_FFT;
        double s, c;
        sincos(ang, &s, &c);
        g_TW[j] = make_float2((float)c, (float)s);
    }
}

// ---------------------------------------------------------------------------
// Zero CBUF (float4 stores)
// ---------------------------------------------------------------------------
__global__ void zero_cbuf_kernel() {
    int i = blockIdx.x * blockDim.x + threadIdx.x;
    const int n4 = BATCH * N_FFT * 2 / 4;  // float2 array as float4
    if (i < n4) {
        reinterpret_cast<float4*>(g_CBUF)[i] = make_float4(0.f, 0.f, 0.f, 0.f);
    }
}

// ---------------------------------------------------------------------------
// Count sketch: CBUF[b][h1[a]].x += s1[a]*x0[b,a];  CBUF[b][h2[a]].y += s2[a]*x1[b,a]
// (packed complex c = p1 + i*p2)
// ---------------------------------------------------------------------------
__global__ void sketch_kernel(const float* __restrict__ x0, const float* __restrict__ x1,
                              const float* __restrict__ s1, const float* __restrict__ s2,
                              const int* __restrict__ h1, const int* __restrict__ h2) {
    int idx = blockIdx.x * blockDim.x + threadIdx.x;
    if (idx >= BATCH * D_IN) return;
    int b = idx / D_IN;
    int a = idx - b * D_IN;
    float v1 = s1[a] * x0[idx];
    float v2 = s2[a] * x1[idx];
    float2* row = g_CBUF + (size_t)b * N_FFT;
    atomicAdd(&row[h1[a]].x, v1);
    atomicAdd(&row[h2[a]].y, v2);
}

// ---------------------------------------------------------------------------
// 16000-pt complex FFT, one CTA per batch row, whole row in smem.
// Four-step: N = 128 * 125.  n = n1*125 + n2 ; k = k1 + 128*k2.
//  Step A: 125 x (128-pt radix-2 DIF over n1, stride 125)  -> slot q holds k1=bitrev7(q)
//  Step B: twiddle W_N^{n2*k1}
//  Step C: 128 x (125-pt DFT over n2) -> write natural-order output to global
// INV=false: input CBUF row (packed sketch) -> output spectrum to CBUF row
// INV=true : input = Z[k]=F1*F2 built from CBUF spectrum -> output real z/N to ZBUF
// ---------------------------------------------------------------------------
template <bool INV>
__global__ __launch_bounds__(512) void fft_kernel() {
    extern __shared__ float2 sm[];
    float2* A    = sm;            // 16000
    float2* W125 = sm + N_FFT;    // 125 (padded to 128)

    const int b   = blockIdx.x;
    const int tid = threadIdx.x;
    const int T   = blockDim.x;   // 512
    float2* row = g_CBUF + (size_t)b * N_FFT;

    // ---- load phase ----
    if (!INV) {
        for (int k = tid; k < N_FFT; k += T) A[k] = row[k];
    } else {
        // build Z[k] = F1[k]*F2[k] from packed spectrum C
        for (int k = tid; k < N_FFT; k += T) {
            float2 C = row[k];
            float2 D = row[k == 0 ? 0 : N_FFT - k];
            float2 F1 = make_float2(0.5f * (C.x + D.x), 0.5f * (C.y - D.y));
            float2 F2 = make_float2(0.5f * (C.y + D.y), 0.5f * (D.x - C.x));
            A[k] = cmulf(F1, F2);
        }
    }
    for (int m = tid; m < 125; m += T) {
        float2 t = g_TW[128 * m];        // W_125^m = W_N^(128 m)
        if (INV) t.y = -t.y;
        W125[m] = t;
    }
    __syncthreads();

    // ---- Step A: radix-2 DIF, 7 stages, 8000 butterflies/stage ----
#pragma unroll
    for (int stage = 0; stage < 7; ++stage) {
        const int L = 128 >> stage;
        const int half = L >> 1;
        const int twstep = 125 << stage;     // W_L^j = W_N^(j * N/L)
        for (int i = tid; i < 8000; i += T) {
            int n2 = i % 125;
            int t  = i / 125;                // 0..63
            int blk = t / half;
            int j   = t - blk * half;
            int p  = (blk * L + j) * 125 + n2;
            int p2 = p + half * 125;
            float2 u = A[p], v = A[p2];
            float2 tw = g_TW[j * twstep];
            if (INV) tw.y = -tw.y;
            A[p]  = make_float2(u.x + v.x, u.y + v.y);
            float2 d = make_float2(u.x - v.x, u.y - v.y);
            A[p2] = cmulf(d, tw);
        }
        __syncthreads();
    }

    // ---- Step B: twiddle W_N^{n2 * k1}, k1 = bitrev7(slot) ----
    for (int p = tid; p < N_FFT; p += T) {
        int q  = p / 125;
        int n2 = p - q * 125;
        int k1 = __brev((unsigned)q) >> 25;
        float2 tw = g_TW[n2 * k1];           // n2*k1 <= 124*127 < 16000
        if (INV) tw.y = -tw.y;
        A[p] = cmulf(A[p], tw);
    }
    __syncthreads();

    // ---- Step C: 125-pt DFTs, output natural order directly to global ----
    for (int oi = tid; oi < N_FFT; oi += T) {
        int q  = oi / 125;
        int k2 = oi - q * 125;
        int k1 = __brev((unsigned)q) >> 25;
        const float2* in = A + q * 125;
        float accx = 0.f, accy = 0.f;
        int e = 0;
#pragma unroll 5
        for (int n2 = 0; n2 < 125; ++n2) {
            float2 tw = W125[e];
            float2 v  = in[n2];
            accx += v.x * tw.x - v.y * tw.y;
            accy += v.x * tw.y + v.y * tw.x;
            e += k2;
            if (e >= 125) e -= 125;
        }
        int outIdx = k1 + 128 * k2;
        if (!INV) {
            row[outIdx] = make_float2(accx, accy);
        } else {
            g_ZBUF[(size_t)b * N_FFT + outIdx] = accx * (1.0f / (float)N_FFT);
        }
    }
}

// ---------------------------------------------------------------------------
// GEMM: out[512,3000] = relu(Z[512,16000] @ W[3000,16000]^T + bias)
// 64x64 tile, BK=16, 64 threads, 8x8 micro-tile (balanced LDS:FMA at FFMA rt=2)
// ---------------------------------------------------------------------------
__global__ __launch_bounds__(64) void gemm_relu_kernel(const float* __restrict__ Wm,
                                                       const float* __restrict__ bias,
                                                       float* __restrict__ out) {
    __shared__ float As[16][64];
    __shared__ float Bs[16][64];

    const int tid = threadIdx.x;       // 0..63
    const int n0 = blockIdx.x * 64;
    const int m0 = blockIdx.y * 64;

    const float* zrow = g_ZBUF + (size_t)(m0 + tid) * KDIM;   // m0+tid < 512 always
    const int nrow = n0 + tid;
    const bool bvalid = nrow < ODIM;
    const float* wrow = Wm + (size_t)nrow * KDIM;

    const int ty = tid >> 3;           // 0..7 -> rows ty*8..ty*8+7
    const int tx = tid & 7;            // 0..7 -> cols tx*8..tx*8+7

    float acc[8][8];
#pragma unroll
    for (int i = 0; i < 8; ++i)
#pragma unroll
        for (int j = 0; j < 8; ++j) acc[i][j] = 0.f;

    const float4 zero4 = make_float4(0.f, 0.f, 0.f, 0.f);

    for (int k0 = 0; k0 < KDIM; k0 += 16) {
        float4 za[4], wb[4];
#pragma unroll
        for (int j = 0; j < 4; ++j) {
            za[j] = *reinterpret_cast<const float4*>(zrow + k0 + 4 * j);
            wb[j] = bvalid ? *reinterpret_cast<const float4*>(wrow + k0 + 4 * j) : zero4;
        }
        __syncthreads();
#pragma unroll
        for (int j = 0; j < 4; ++j) {
            As[4 * j + 0][tid] = za[j].x;
            As[4 * j + 1][tid] = za[j].y;
            As[4 * j + 2][tid] = za[j].z;
            As[4 * j + 3][tid] = za[j].w;
            Bs[4 * j + 0][tid] = wb[j].x;
            Bs[4 * j + 1][tid] = wb[j].y;
            Bs[4 * j + 2][tid] = wb[j].z;
            Bs[4 * j + 3][tid] = wb[j].w;
        }
        __syncthreads();
#pragma unroll
        for (int kk = 0; kk < 16; ++kk) {
            float4 a0 = *reinterpret_cast<const float4*>(&As[kk][ty * 8]);
            float4 a1 = *reinterpret_cast<const float4*>(&As[kk][ty * 8 + 4]);
            float4 b0 = *reinterpret_cast<const float4*>(&Bs[kk][tx * 8]);
            float4 b1 = *reinterpret_cast<const float4*>(&Bs[kk][tx * 8 + 4]);
            float av[8] = {a0.x, a0.y, a0.z, a0.w, a1.x, a1.y, a1.z, a1.w};
            float bv[8] = {b0.x, b0.y, b0.z, b0.w, b1.x, b1.y, b1.z, b1.w};
#pragma unroll
            for (int i = 0; i < 8; ++i)
#pragma unroll
                for (int j = 0; j < 8; ++j) acc[i][j] = fmaf(av[i], bv[j], acc[i][j]);
        }
    }

    // epilogue: bias + relu
#pragma unroll
    for (int i = 0; i < 8; ++i) {
        int m = m0 + ty * 8 + i;
#pragma unroll
        for (int j = 0; j < 8; ++j) {
            int n = n0 + tx * 8 + j;
            if (n < ODIM) {
                float v = acc[i][j] + bias[n];
                out[(size_t)m * ODIM + n] = v > 0.f ? v : 0.f;
            }
        }
    }
}

// ---------------------------------------------------------------------------
extern "C" void kernel_launch(void* const* d_in, const int* in_sizes, int n_in,
                              void* d_out, int out_size) {
    const float* x0  = (const float*)d_in[0];
    const float* x1  = (const float*)d_in[1];
    const float* s1  = (const float*)d_in[2];
    const float* s2  = (const float*)d_in[3];
    const float* Wm  = (const float*)d_in[4];
    const float* bia = (const float*)d_in[5];
    const int*   h1  = (const int*)d_in[6];
    const int*   h2  = (const int*)d_in[7];
    float* out = (float*)d_out;

    const int FFT_SMEM = (N_FFT + 128) * (int)sizeof(float2);  // 129 KB

    cudaFuncSetAttribute(fft_kernel<false>, cudaFuncAttributeMaxDynamicSharedMemorySize, FFT_SMEM);
    cudaFuncSetAttribute(fft_kernel<true>,  cudaFuncAttributeMaxDynamicSharedMemorySize, FFT_SMEM);

    tw_init_kernel<<<(N_FFT + 255) / 256, 256>>>();

    const int n4 = BATCH * N_FFT * 2 / 4;
    zero_cbuf_kernel<<<(n4 + 255) / 256, 256>>>();

    sketch_kernel<<<(BATCH * D_IN + 255) / 256, 256>>>(x0, x1, s1, s2, h1, h2);

    fft_kernel<false><<<BATCH, 512, FFT_SMEM>>>();
    fft_kernel<true><<<BATCH, 512, FFT_SMEM>>>();

    gemm_relu_kernel<<<dim3((ODIM + 63) / 64, BATCH / 64), 64>>>(Wm, bia, out);
}

// round 6
// speedup vs baseline: 3.5799x; 3.5799x over previous
#include <cuda_runtime.h>
#include <cuda_bf16.h>
#include <cstdint>
#include <cstddef>
#include <math.h>

#define N_FFT   16000
#define BATCH   512
#define D_IN    2048
#define ODIM    3000
#define KDIM    16000

// Scratch (device globals — allocation-free per harness rules)
__device__ float2 g_CBUF[BATCH * N_FFT];   // 64 MB: packed sketch / spectrum
__device__ float  g_ZBUF[BATCH * N_FFT];   // 32 MB: conv result z (fp32)
__device__ float2 g_TW[N_FFT];             // twiddle table exp(-2*pi*i*j/N)

static __device__ __forceinline__ float2 cmulf(float2 a, float2 b) {
    return make_float2(a.x * b.x - a.y * b.y, a.x * b.y + a.y * b.x);
}

static __device__ __forceinline__ unsigned smem_u32(const void* p) {
    unsigned a;
    asm("{ .reg .u64 t; cvta.to.shared.u64 t, %1; cvt.u32.u64 %0, t; }" : "=r"(a) : "l"(p));
    return a;
}

// SW128 swizzle: XOR bits [6:4] with bits [9:7]
static __device__ __forceinline__ unsigned swz128(unsigned off) {
    return off ^ ((off >> 3) & 0x70);
}

// ---------------------------------------------------------------------------
__global__ void tw_init_kernel() {
    int j = blockIdx.x * blockDim.x + threadIdx.x;
    if (j < N_FFT) {
        double ang = -2.0 * 3.14159265358979323846 * (double)j / (double)N_FFT;
        double s, c;
        sincos(ang, &s, &c);
        g_TW[j] = make_float2((float)c, (float)s);
    }
}

__global__ void zero_cbuf_kernel() {
    int i = blockIdx.x * blockDim.x + threadIdx.x;
    const int n4 = BATCH * N_FFT * 2 / 4;
    if (i < n4) {
        reinterpret_cast<float4*>(g_CBUF)[i] = make_float4(0.f, 0.f, 0.f, 0.f);
    }
}

// ---------------------------------------------------------------------------
// Count sketch (packed complex c = p1 + i*p2)
// ---------------------------------------------------------------------------
__global__ void sketch_kernel(const float* __restrict__ x0, const float* __restrict__ x1,
                              const float* __restrict__ s1, const float* __restrict__ s2,
                              const int* __restrict__ h1, const int* __restrict__ h2) {
    int idx = blockIdx.x * blockDim.x + threadIdx.x;
    if (idx >= BATCH * D_IN) return;
    int b = idx / D_IN;
    int a = idx - b * D_IN;
    float v1 = s1[a] * x0[idx];
    float v2 = s2[a] * x1[idx];
    float2* row = g_CBUF + (size_t)b * N_FFT;
    atomicAdd(&row[h1[a]].x, v1);
    atomicAdd(&row[h2[a]].y, v2);
}

// ---------------------------------------------------------------------------
// 16000-pt complex FFT, one CTA per batch row, whole row in smem.
// N = 128 * 125.  n = n1*125 + n2 ; k = k1 + 128*k2.
//  Step A: 125 x (128-pt radix-2 DIF over n1)  -> chunk q holds k1=bitrev7(q)
//  Step B: twiddle W_N^{n2*k1}
//  Step C: 128 x (125-pt DFT via 3 radix-5 DIF stages) -> k2 = rev5(slot)
// ---------------------------------------------------------------------------
template <bool INV>
__global__ __launch_bounds__(512) void fft_kernel() {
    extern __shared__ float2 sm[];
    float2* A    = sm;            // 16000
    float2* W125 = sm + N_FFT;    // 125

    const int b   = blockIdx.x;
    const int tid = threadIdx.x;
    const int T   = blockDim.x;   // 512
    float2* row = g_CBUF + (size_t)b * N_FFT;

    // ---- load phase ----
    if (!INV) {
        for (int k = tid; k < N_FFT; k += T) A[k] = row[k];
    } else {
        for (int k = tid; k < N_FFT; k += T) {
            float2 C = row[k];
            float2 D = row[k == 0 ? 0 : N_FFT - k];
            float2 F1 = make_float2(0.5f * (C.x + D.x), 0.5f * (C.y - D.y));
            float2 F2 = make_float2(0.5f * (C.y + D.y), 0.5f * (D.x - C.x));
            A[k] = cmulf(F1, F2);
        }
    }
    for (int m = tid; m < 125; m += T) {
        float2 t = g_TW[128 * m];        // W_125^m
        if (INV) t.y = -t.y;
        W125[m] = t;
    }
    __syncthreads();

    // ---- Step A: radix-2 DIF, 7 stages ----
#pragma unroll
    for (int stage = 0; stage < 7; ++stage) {
        const int L = 128 >> stage;
        const int half = L >> 1;
        const int twstep = 125 << stage;
        for (int i = tid; i < 8000; i += T) {
            int n2 = i % 125;
            int t  = i / 125;
            int blk = t / half;
            int j   = t - blk * half;
            int p  = (blk * L + j) * 125 + n2;
            int p2 = p + half * 125;
            float2 u = A[p], v = A[p2];
            float2 tw = g_TW[j * twstep];
            if (INV) tw.y = -tw.y;
            A[p]  = make_float2(u.x + v.x, u.y + v.y);
            float2 d = make_float2(u.x - v.x, u.y - v.y);
            A[p2] = cmulf(d, tw);
        }
        __syncthreads();
    }

    // ---- Step B: twiddle W_N^{n2 * k1}, k1 = bitrev7(chunk) ----
    for (int p = tid; p < N_FFT; p += T) {
        int q  = p / 125;
        int n2 = p - q * 125;
        int k1 = __brev((unsigned)q) >> 25;
        float2 tw = g_TW[n2 * k1];
        if (INV) tw.y = -tw.y;
        A[p] = cmulf(A[p], tw);
    }
    __syncthreads();

    // ---- Step C: 3 radix-5 DIF stages per 125-chunk ----
    {
        const float c1 = 0.309016994374947424f;   // cos(2pi/5)
        const float c2 = -0.809016994374947424f;  // cos(4pi/5)
        const float S1 = INV ? -0.951056516295153572f : 0.951056516295153572f;
        const float S2 = INV ? -0.587785252292473129f : 0.587785252292473129f;
        const int Ls[3]   = {125, 25, 5};
        const int subs[3] = {25, 5, 1};
        const int fs[3]   = {1, 5, 25};
#pragma unroll
        for (int s = 0; s < 3; ++s) {
            const int L = Ls[s], sub = subs[s], f = fs[s];
            for (int i = tid; i < 3200; i += T) {
                int q = i / 25;
                int t = i - q * 25;
                int blk = t / sub;
                int j   = t - blk * sub;
                int base = q * 125 + blk * L + j;
                float2 x0 = A[base];
                float2 x1 = A[base + sub];
                float2 x2 = A[base + 2 * sub];
                float2 x3 = A[base + 3 * sub];
                float2 x4 = A[base + 4 * sub];
                float t1x = x1.x + x4.x, t1y = x1.y + x4.y;
                float t2x = x2.x + x3.x, t2y = x2.y + x3.y;
                float t3x = x1.x - x4.x, t3y = x1.y - x4.y;
                float t4x = x2.x - x3.x, t4y = x2.y - x3.y;
                float2 y0 = make_float2(x0.x + t1x + t2x, x0.y + t1y + t2y);
                float ax = x0.x + c1 * t1x + c2 * t2x;
                float ay = x0.y + c1 * t1y + c2 * t2y;
                float bx = S1 * t3x + S2 * t4x;
                float by = S1 * t3y + S2 * t4y;
                float dx = x0.x + c2 * t1x + c1 * t2x;
                float dy = x0.y + c2 * t1y + c1 * t2y;
                float ex = S2 * t3x - S1 * t4x;
                float ey = S2 * t3y - S1 * t4y;
                float2 y1 = make_float2(ax + by, ay - bx);   // a - i b
                float2 y4 = make_float2(ax - by, ay + bx);   // a + i b
                float2 y2 = make_float2(dx + ey, dy - ex);   // d - i e
                float2 y3 = make_float2(dx - ey, dy + ex);   // d + i e
                int jf = j * f;
                A[base]           = y0;
                A[base + sub]     = cmulf(y1, W125[jf]);
                A[base + 2 * sub] = cmulf(y2, W125[2 * jf]);
                A[base + 3 * sub] = cmulf(y3, W125[3 * jf]);
                A[base + 4 * sub] = cmulf(y4, W125[4 * jf]);
            }
            __syncthreads();
        }
    }

    // ---- write out: slot j holds k2 = rev5(j); chunk q holds k1 = bitrev7(q) ----
    for (int oi = tid; oi < N_FFT; oi += T) {
        int q = oi / 125;
        int j = oi - q * 125;
        int k1 = __brev((unsigned)q) >> 25;
        int d0 = j % 5, jr = j / 5;
        int d1 = jr % 5, d2 = jr / 5;
        int k2 = d0 * 25 + d1 * 5 + d2;
        float2 v = A[oi];
        int outIdx = k1 + 128 * k2;
        if (!INV) {
            row[outIdx] = v;
        } else {
            g_ZBUF[(size_t)b * N_FFT + outIdx] = v.x * (1.0f / (float)N_FFT);
        }
    }
}

// ---------------------------------------------------------------------------
// HMMA bf16 split-precision GEMM (mma.sync m16n8k16 — family-common, no tcgen05):
//   out[512,3000] = relu(Z @ W^T + b)
//   fp32 -> (hi,lo) bf16; accumulate zhi*whi + zhi*wlo + zlo*whi in fp32.
// Tile 128x128, TK=32, 8 warps (4m x 2n; warp tile 32x64), double-buffered smem.
// smem row layout per m/n index: 128B = [hi k0..31 | lo k0..31], SW128 swizzle.
// ---------------------------------------------------------------------------
#define GTK 32
#define GITERS (KDIM / GTK)        // 500
#define STG_A 16384                // 128 rows x 128 B
#define STG_BYTES 32768            // A + B
#define GEMM_SMEM (2 * STG_BYTES)  // 64 KB

static __device__ __forceinline__ void bf16_split_pack(float x, float y,
                                                       unsigned& hi, unsigned& lo) {
    __nv_bfloat16 hx = __float2bfloat16_rn(x);
    __nv_bfloat16 hy = __float2bfloat16_rn(y);
    __nv_bfloat16 lx = __float2bfloat16_rn(x - __bfloat162float(hx));
    __nv_bfloat16 ly = __float2bfloat16_rn(y - __bfloat162float(hy));
    hi = ((unsigned)__bfloat16_as_ushort(hy) << 16) | __bfloat16_as_ushort(hx);
    lo = ((unsigned)__bfloat16_as_ushort(ly) << 16) | __bfloat16_as_ushort(lx);
}

// store float4 (4 consecutive k) for row r: hi at row*128 + seg*8, lo at +64
static __device__ __forceinline__ void split_store_row(char* base, unsigned rowByte,
                                                       unsigned segByte, float4 v) {
    unsigned h0, l0, h1, l1;
    bf16_split_pack(v.x, v.y, h0, l0);
    bf16_split_pack(v.z, v.w, h1, l1);
    *reinterpret_cast<uint2*>(base + swz128(rowByte + segByte)) = make_uint2(h0, h1);
    *reinterpret_cast<uint2*>(base + swz128(rowByte + 64 + segByte)) = make_uint2(l0, l1);
}

static __device__ __forceinline__ void ldsm_x4(unsigned addr, unsigned* r) {
    asm volatile("ldmatrix.sync.aligned.m8n8.x4.shared.b16 {%0,%1,%2,%3}, [%4];"
                 : "=r"(r[0]), "=r"(r[1]), "=r"(r[2]), "=r"(r[3]) : "r"(addr));
}

static __device__ __forceinline__ void mma_bf16(float* c, const unsigned* a, const unsigned* b) {
    asm volatile(
        "mma.sync.aligned.m16n8k16.row.col.f32.bf16.bf16.f32 "
        "{%0,%1,%2,%3}, {%4,%5,%6,%7}, {%8,%9}, {%0,%1,%2,%3};"
        : "+f"(c[0]), "+f"(c[1]), "+f"(c[2]), "+f"(c[3])
        : "r"(a[0]), "r"(a[1]), "r"(a[2]), "r"(a[3]), "r"(b[0]), "r"(b[1]));
}

__global__ __launch_bounds__(256, 1) void gemm_hmma_kernel(const float* __restrict__ Wm,
                                                           const float* __restrict__ bias,
                                                           float* __restrict__ out) {
    extern __shared__ char gsm[];
    const unsigned sbase = smem_u32(gsm);
    const int tid  = threadIdx.x;
    const int lane = tid & 31;
    const int wid  = tid >> 5;
    const int wm   = wid >> 1;          // 0..3
    const int wn   = wid & 1;           // 0..1
    const int n0 = blockIdx.x * 128;
    const int m0 = blockIdx.y * 128;

    // per-thread load coords: 4 float4 per matrix per chunk
    // lin = i*256 + tid : r = lin>>3 (0..127), seg = lin&7
    float acc[2][8][4];
#pragma unroll
    for (int i = 0; i < 2; ++i)
#pragma unroll
        for (int j = 0; j < 8; ++j)
#pragma unroll
            for (int e = 0; e < 4; ++e) acc[i][j][e] = 0.f;

    float4 pa[4], pb[4];

    // ---- prologue: load + store chunk 0 into stage 0 ----
#pragma unroll
    for (int i = 0; i < 4; ++i) {
        int lin = i * 256 + tid;
        int r = lin >> 3, seg = lin & 7;
        pa[i] = *reinterpret_cast<const float4*>(g_ZBUF + (size_t)(m0 + r) * KDIM + seg * 4);
        int wr = n0 + r;
        pb[i] = (wr < ODIM) ? *reinterpret_cast<const float4*>(Wm + (size_t)wr * KDIM + seg * 4)
                            : make_float4(0.f, 0.f, 0.f, 0.f);
    }
#pragma unroll
    for (int i = 0; i < 4; ++i) {
        int lin = i * 256 + tid;
        int r = lin >> 3, seg = lin & 7;
        split_store_row(gsm, (unsigned)(r * 128), (unsigned)(seg * 8), pa[i]);
        split_store_row(gsm + STG_A, (unsigned)(r * 128), (unsigned)(seg * 8), pb[i]);
    }
    __syncthreads();

    for (int c = 0; c < GITERS; ++c) {
        const int s = c & 1;
        const bool more = (c + 1) < GITERS;
        // prefetch next chunk into registers
        if (more) {
            const int k0 = (c + 1) * GTK;
#pragma unroll
            for (int i = 0; i < 4; ++i) {
                int lin = i * 256 + tid;
                int r = lin >> 3, seg = lin & 7;
                pa[i] = *reinterpret_cast<const float4*>(
                    g_ZBUF + (size_t)(m0 + r) * KDIM + k0 + seg * 4);
                int wr = n0 + r;
                pb[i] = (wr < ODIM)
                    ? *reinterpret_cast<const float4*>(Wm + (size_t)wr * KDIM + k0 + seg * 4)
                    : make_float4(0.f, 0.f, 0.f, 0.f);
            }
        }

        // ---- compute on stage s ----
        const unsigned Ab = sbase + s * STG_BYTES;
        const unsigned Bb = Ab + STG_A;
#pragma unroll
        for (int ks = 0; ks < 2; ++ks) {
            unsigned Af[2][2][4];   // [plane][mfrag]
            unsigned Bf[2][4][4];   // [plane][ngroup] -> {b0 n0-7, b1 n0-7, b0 n8-15, b1 n8-15}
#pragma unroll
            for (int p = 0; p < 2; ++p) {
#pragma unroll
                for (int mf = 0; mf < 2; ++mf) {
                    int row = wm * 32 + mf * 16 + (lane & 15);
                    unsigned off = (unsigned)(row * 128 + p * 64 + ks * 32 + ((lane >> 4) << 4));
                    ldsm_x4(Ab + swz128(off), Af[p][mf]);
                }
#pragma unroll
                for (int g = 0; g < 4; ++g) {
                    int row = wn * 64 + g * 16 + ((lane & 7) | (((lane >> 4) & 1) << 3));
                    unsigned off = (unsigned)(row * 128 + p * 64 + ks * 32 + (((lane >> 3) & 1) << 4));
                    ldsm_x4(Bb + swz128(off), Bf[p][g]);
                }
            }
            // 3 terms: (Aplane, Bplane) = (0,0), (0,1), (1,0)
#pragma unroll
            for (int t = 0; t < 3; ++t) {
                const int ap = (t == 2) ? 1 : 0;
                const int bp = (t == 1) ? 1 : 0;
#pragma unroll
                for (int mf = 0; mf < 2; ++mf)
#pragma unroll
                    for (int nf = 0; nf < 8; ++nf) {
                        mma_bf16(acc[mf][nf], Af[ap][mf], &Bf[bp][nf >> 1][(nf & 1) * 2]);
                    }
            }
        }

        // ---- store prefetched chunk into other stage ----
        if (more) {
            char* dst = gsm + (s ^ 1) * STG_BYTES;
#pragma unroll
            for (int i = 0; i < 4; ++i) {
                int lin = i * 256 + tid;
                int r = lin >> 3, seg = lin & 7;
                split_store_row(dst, (unsigned)(r * 128), (unsigned)(seg * 8), pa[i]);
                split_store_row(dst + STG_A, (unsigned)(r * 128), (unsigned)(seg * 8), pb[i]);
            }
        }
        __syncthreads();
    }

    // ---- epilogue: bias + relu, write out ----
#pragma unroll
    for (int mf = 0; mf < 2; ++mf) {
        int mlo = m0 + wm * 32 + mf * 16 + (lane >> 2);
#pragma unroll
        for (int nf = 0; nf < 8; ++nf) {
            int n = n0 + wn * 64 + nf * 8 + 2 * (lane & 3);
            if (n < ODIM) {
                float b0 = bias[n], b1 = bias[n + 1];
                float2 v0, v1;
                v0.x = fmaxf(acc[mf][nf][0] + b0, 0.f);
                v0.y = fmaxf(acc[mf][nf][1] + b1, 0.f);
                v1.x = fmaxf(acc[mf][nf][2] + b0, 0.f);
                v1.y = fmaxf(acc[mf][nf][3] + b1, 0.f);
                *reinterpret_cast<float2*>(out + (size_t)mlo * ODIM + n) = v0;
                *reinterpret_cast<float2*>(out + (size_t)(mlo + 8) * ODIM + n) = v1;
            }
        }
    }
}

// ---------------------------------------------------------------------------
extern "C" void kernel_launch(void* const* d_in, const int* in_sizes, int n_in,
                              void* d_out, int out_size) {
    const float* x0  = (const float*)d_in[0];
    const float* x1  = (const float*)d_in[1];
    const float* s1  = (const float*)d_in[2];
    const float* s2  = (const float*)d_in[3];
    const float* Wm  = (const float*)d_in[4];
    const float* bia = (const float*)d_in[5];
    const int*   h1  = (const int*)d_in[6];
    const int*   h2  = (const int*)d_in[7];
    float* out = (float*)d_out;

    const int FFT_SMEM = (N_FFT + 128) * (int)sizeof(float2);  // 129 KB

    cudaFuncSetAttribute(fft_kernel<false>, cudaFuncAttributeMaxDynamicSharedMemorySize, FFT_SMEM);
    cudaFuncSetAttribute(fft_kernel<true>,  cudaFuncAttributeMaxDynamicSharedMemorySize, FFT_SMEM);
    cudaFuncSetAttribute(gemm_hmma_kernel, cudaFuncAttributeMaxDynamicSharedMemorySize, GEMM_SMEM);

    tw_init_kernel<<<(N_FFT + 255) / 256, 256>>>();

    const int n4 = BATCH * N_FFT * 2 / 4;
    zero_cbuf_kernel<<<(n4 + 255) / 256, 256>>>();

    sketch_kernel<<<(BATCH * D_IN + 255) / 256, 256>>>(x0, x1, s1, s2, h1, h2);

    fft_kernel<false><<<BATCH, 512, FFT_SMEM>>>();
    fft_kernel<true><<<BATCH, 512, FFT_SMEM>>>();

    gemm_hmma_kernel<<<dim3((ODIM + 127) / 128, BATCH / 128), 256, GEMM_SMEM>>>(Wm, bia, out);
}